// round 12
// baseline (speedup 1.0000x reference)
#include <cuda_runtime.h>
#include <cstdint>

// Problem shapes (fixed by dataset)
#define BATCH 128
#define CHAN  2048
#define PP    14          // spatial extent
#define HW    196         // 14*14
#define NBOX  36
#define CC    32          // channels per block
#define CHUNK 16          // channels per TMA pipeline stage (2 stages)
#define NTHREADS 512
#define CH_BYTES (HW * 4)         // 784 B per channel row (16B multiple)
#define TSTRIDE  208              // floats per channel in smem (16B multiple)
#define RW    15                  // row-prefix width (P+1)
#define RSTR  211                 // rpf channel stride: 211 % 32 = 19 -> conflict-free
#define TILE_FLOATS (TSTRIDE * 32 + 64)   // 6720: covers max base 6504 + 196
#define RPF_FLOATS  (RSTR * CC)           // 6752
#define SMEM_BYTES  ((TILE_FLOATS + RPF_FLOATS) * sizeof(float))  // 53,888 B -> 4 CTAs/SM

// Channel base in floats. Stagger 8*((c>>2)&3) makes the att gather bank set
// {16(k&1) + 8*c4 + hw} = all 32 banks; the 32*(c>>4) term (== 0 mod 32 banks)
// restores a >=216-float gap at the c=16 stagger wrap so TMA regions never
// overlap (R11's bug: gap was 184 < 196 there).
__device__ __forceinline__ int chan_base(int c) {
    return TSTRIDE * c + 8 * ((c >> 2) & 3) + 32 * (c >> 4);
}

__device__ __forceinline__ uint32_t smem_u32(const void* p) {
    return (uint32_t)__cvta_generic_to_shared(p);
}

__device__ __forceinline__ void mbar_wait(uint32_t mbar_a) {
    uint32_t done;
    asm volatile(
        "{\n\t.reg .pred p;\n\t"
        "mbarrier.try_wait.parity.acquire.cta.shared::cta.b64 p, [%1], %2;\n\t"
        "selp.b32 %0, 1, 0, p;\n\t}"
        : "=r"(done) : "r"(mbar_a), "r"(0) : "memory");
    if (!done) {
        asm volatile(
            "{\n\t.reg .pred P1;\n\t"
            "W_%=:\n\t"
            "mbarrier.try_wait.parity.acquire.cta.shared::cta.b64 P1, [%0], %1, 0x989680;\n\t"
            "@P1 bra.uni D_%=;\n\t"
            "bra.uni W_%=;\n\t"
            "D_%=:\n\t}"
            :: "r"(mbar_a), "r"(0) : "memory");
    }
}

__global__ __launch_bounds__(NTHREADS, 4)
void fused_pool_transpose_region(
    const float* __restrict__ images,   // [B, C, 14, 14]
    const float* __restrict__ boxes,    // [B, 36, 4]
    float* __restrict__ fc,             // [B, C]
    float* __restrict__ att,            // [B, 196, C]
    float* __restrict__ bu)             // [B, 36, C]
{
    extern __shared__ float smem[];
    float* tile = smem;                 // per-channel linear rows, staggered
    float* rpf  = smem + TILE_FLOATS;   // [CC][RSTR]: rpf[c][y*15+x] row prefix

    __shared__ int   bx1[NBOX], by1[NBOX], bx2[NBOX], by2[NBOX];
    __shared__ float barea[NBOX];
    __shared__ alignas(8) unsigned long long mbar[2];

    const int b   = blockIdx.y;
    const int c0  = blockIdx.x * CC;
    const int tid = threadIdx.x;

    const float* img = images + ((size_t)b * CHAN + c0) * HW;

    if (tid < 2) {
        asm volatile("mbarrier.init.shared.b64 [%0], %1;"
                     :: "r"(smem_u32(&mbar[tid])), "r"(1) : "memory");
    }

    // ---- box coordinates (replicates reference rounding/degenerate fix) ----
    if (tid < NBOX) {
        const float* bp = boxes + ((size_t)b * NBOX + tid) * 4;
        int x1 = (int)rintf(bp[0] * (float)PP);   // round-half-even == jnp.round
        int y1 = (int)rintf(bp[1] * (float)PP);
        int x2 = (int)rintf(bp[2] * (float)PP);
        int y2 = (int)rintf(bp[3] * (float)PP);
        bool eqx = (x1 == x2);
        if (eqx && x2 <  PP) x2 += 1;
        if (eqx && x2 >= PP && x1 > 0 && x1 == x2) x1 -= 1;
        bool eqy = (y1 == y2);
        if (eqy && y2 <  PP) y2 += 1;
        if (eqy && y2 >= PP && y1 > 0 && y1 == y2) y1 -= 1;
        bx1[tid] = x1; by1[tid] = y1; bx2[tid] = x2; by2[tid] = y2;
        barea[tid] = (float)((y2 - y1) * (x2 - x1));
    }
    __syncthreads();   // mbarrier init + boxes visible

    // ---- issue both TMA half-tiles upfront; half k completes on mbar[k] ----
    if (tid < 2) {
        asm volatile("mbarrier.arrive.expect_tx.shared.b64 _, [%0], %1;"
                     :: "r"(smem_u32(&mbar[tid])),
                        "r"((uint32_t)(CHUNK * CH_BYTES)) : "memory");
    }
    if (tid < CC) {   // thread tid copies channel tid; half = tid>>4
        uint32_t dst = smem_u32(tile + chan_base(tid));
        const float* src = img + (size_t)tid * HW;
        asm volatile(
            "cp.async.bulk.shared::cluster.global.mbarrier::complete_tx::bytes "
            "[%0], [%1], %2, [%3];"
            :: "r"(dst), "l"(src), "r"((uint32_t)CH_BYTES),
               "r"(smem_u32(&mbar[tid >> 4])) : "memory");
    }

    // ---- pipelined halves: write half k's att stream while half k+1 loads ----
    float* attb = att + (size_t)b * HW * CHAN + c0;
    #pragma unroll
    for (int half = 0; half < 2; half++) {
        mbar_wait(smem_u32(&mbar[half]));
        const int ho = half * CHUNK;

        // att transpose: c4 = tid&3 invariant (512 % 4 == 0), hw strided 128.
        // 4 conflict-free LDS -> 1 STG.128 (64B per-warp segments).
        {
            const int c4  = tid & 3;
            const int hw0 = tid >> 2;                  // 0..127
            const float* t0 = tile + chan_base(ho + 4 * c4 + 0);
            const float* t1 = tile + chan_base(ho + 4 * c4 + 1);
            const float* t2 = tile + chan_base(ho + 4 * c4 + 2);
            const float* t3 = tile + chan_base(ho + 4 * c4 + 3);
            float* a = attb + (size_t)hw0 * CHAN + ho + 4 * c4;
            #pragma unroll
            for (int hw = hw0; hw < HW; hw += 128, a += 128 * CHAN) {
                float4 v;
                v.x = t0[hw]; v.y = t1[hw]; v.z = t2[hw]; v.w = t3[hw];
                *(float4*)a = v;
            }
        }

        // row prefix for this half: thread per (c, y), 224 active
        if (tid < CHUNK * PP) {
            int cl = tid / PP, y = tid - cl * PP;
            int c = ho + cl;
            const float* tc  = tile + chan_base(c) + y * PP;
            float*       dst = rpf  + c * RSTR + y * RW;
            dst[0] = 0.0f;
            float acc = 0.0f;
            #pragma unroll
            for (int x = 0; x < PP; x++) { acc += tc[x]; dst[x + 1] = acc; }
        }
    }
    __syncthreads();

    // ---- fc: column-sum of full row sums / 196 (one warp, lanes = c) ----
    if (tid < CC) {
        const float* Rc = rpf + tid * RSTR;
        float s = 0.0f;
        #pragma unroll
        for (int y = 0; y < PP; y++) s += Rc[y * RW + PP];
        fc[(size_t)b * CHAN + c0 + tid] = s * (1.0f / (float)HW);
    }

    // ---- bu: vertical accumulation of row-prefix diffs; warp = box, lane = c
    //      (stride 211 == 19 mod 32 -> conflict-free), uniform y trip count ----
    {
        float* bub = bu + (size_t)b * NBOX * CHAN + c0;
        for (int i = tid; i < NBOX * CC; i += NTHREADS) {
            int r = i >> 5, c = i & 31;
            const float* Rc = rpf + c * RSTR;
            int x1 = bx1[r], y1 = by1[r], x2 = bx2[r], y2 = by2[r];
            float s = 0.0f;
            for (int y = y1; y < y2; y++)
                s += Rc[y * RW + x2] - Rc[y * RW + x1];
            bub[(size_t)r * CHAN + c] = s / barea[r];
        }
    }
}

extern "C" void kernel_launch(void* const* d_in, const int* in_sizes, int n_in,
                              void* d_out, int out_size)
{
    const float* images = (const float*)d_in[0];
    const float* boxes  = (const float*)d_in[1];

    float* out = (float*)d_out;
    float* fc  = out;                                   // [128, 2048]
    float* att = fc  + (size_t)BATCH * CHAN;            // [128, 196, 2048]
    float* bu  = att + (size_t)BATCH * HW * CHAN;       // [128, 36, 2048]

    cudaFuncSetAttribute(fused_pool_transpose_region,
                         cudaFuncAttributeMaxDynamicSharedMemorySize,
                         (int)SMEM_BYTES);

    dim3 grid(CHAN / CC, BATCH);
    fused_pool_transpose_region<<<grid, NTHREADS, SMEM_BYTES>>>(
        images, boxes, fc, att, bu);
}

// round 13
// speedup vs baseline: 1.0625x; 1.0625x over previous
#include <cuda_runtime.h>
#include <cstdint>

// Problem shapes (fixed by dataset)
#define BATCH 128
#define CHAN  2048
#define PP    14          // spatial extent
#define HW    196         // 14*14
#define NBOX  36
#define CC    32          // channels per tile
#define NTILES (BATCH * (CHAN / CC))   // 8192
#define NTHREADS 512
#define GRID   296        // 2 CTAs x 148 SMs resident -> persistent
#define CH_BYTES (HW * 4)         // 784 B per channel row (16B multiple)
#define TSTRIDE  208              // floats per channel in smem (16B multiple)
#define RW    15                  // row-prefix width (P+1)
#define RSTR  211                 // rpf channel stride: 211 % 32 = 19 -> conflict-free
#define BUF_FLOATS 6688           // max chan_base 6476 + 196, padded to 16B multiple
#define RPF_FLOATS (RSTR * CC)    // 6752
#define SMEM_BYTES ((2 * BUF_FLOATS + RPF_FLOATS) * sizeof(float))  // 80,512 B -> 2 CTAs/SM

// R10-proven layout: linear channel rows + monotone 16B stagger.
// att gather bank set (c4 = tid&7 mapping) covers all 32 banks; adjacent
// channel gap is 208 or 212 floats >= 196 -> TMA regions never overlap.
__device__ __forceinline__ int chan_base(int c) {
    return TSTRIDE * c + 4 * ((c >> 2) & 7);
}

__device__ __forceinline__ uint32_t smem_u32(const void* p) {
    return (uint32_t)__cvta_generic_to_shared(p);
}

__device__ __forceinline__ void mbar_wait(uint32_t mbar_a, uint32_t parity) {
    uint32_t done;
    asm volatile(
        "{\n\t.reg .pred p;\n\t"
        "mbarrier.try_wait.parity.acquire.cta.shared::cta.b64 p, [%1], %2;\n\t"
        "selp.b32 %0, 1, 0, p;\n\t}"
        : "=r"(done) : "r"(mbar_a), "r"(parity) : "memory");
    if (!done) {
        asm volatile(
            "{\n\t.reg .pred P1;\n\t"
            "W_%=:\n\t"
            "mbarrier.try_wait.parity.acquire.cta.shared::cta.b64 P1, [%0], %1, 0x989680;\n\t"
            "@P1 bra.uni D_%=;\n\t"
            "bra.uni W_%=;\n\t"
            "D_%=:\n\t}"
            :: "r"(mbar_a), "r"(parity) : "memory");
    }
}

__global__ __launch_bounds__(NTHREADS, 2)
void fused_pool_transpose_region(
    const float* __restrict__ images,   // [B, C, 14, 14]
    const float* __restrict__ boxes,    // [B, 36, 4]
    float* __restrict__ fc,             // [B, C]
    float* __restrict__ att,            // [B, 196, C]
    float* __restrict__ bu)             // [B, 36, C]
{
    extern __shared__ float smem[];
    float* rpf = smem + 2 * BUF_FLOATS;   // [CC][RSTR]: row prefix scratch

    __shared__ int   bx1[NBOX], by1[NBOX], bx2[NBOX], by2[NBOX];
    __shared__ float barea[NBOX];
    __shared__ alignas(8) unsigned long long mbar[2];

    const int tid = threadIdx.x;

    if (tid < 2) {
        asm volatile("mbarrier.init.shared.b64 [%0], %1;"
                     :: "r"(smem_u32(&mbar[tid])), "r"(1) : "memory");
    }
    __syncthreads();   // mbarrier init visible

    // ---- prologue: issue TMA for first tile into buf 0 ----
    {
        int t = blockIdx.x;            // first tile (GRID < NTILES always)
        int b = t >> 6, c0 = (t & 63) * CC;
        const float* img = images + ((size_t)b * CHAN + c0) * HW;
        if (tid == 0) {
            asm volatile("mbarrier.arrive.expect_tx.shared.b64 _, [%0], %1;"
                         :: "r"(smem_u32(&mbar[0])),
                            "r"((uint32_t)(CC * CH_BYTES)) : "memory");
        }
        __syncwarp();
        if (tid < CC) {
            asm volatile(
                "cp.async.bulk.shared::cluster.global.mbarrier::complete_tx::bytes "
                "[%0], [%1], %2, [%3];"
                :: "r"(smem_u32(smem + chan_base(tid))),
                   "l"(img + (size_t)tid * HW), "r"((uint32_t)CH_BYTES),
                   "r"(smem_u32(&mbar[0])) : "memory");
        }
    }

    int k = 0;
    for (int t = blockIdx.x; t < NTILES; t += GRID, k++) {
        const int buf_i = k & 1;
        float* tile = smem + buf_i * BUF_FLOATS;

        // ---- issue TMA for next tile into the spare buffer (drained since
        //      end of iter k-1; its mbarrier phase flipped at iter k-1 wait) ----
        {
            int tn = t + GRID;
            if (tn < NTILES) {
                int nb = tn >> 6, nc0 = (tn & 63) * CC;
                const float* nimg = images + ((size_t)nb * CHAN + nc0) * HW;
                uint32_t nm = smem_u32(&mbar[buf_i ^ 1]);
                float* nbuf = smem + (buf_i ^ 1) * BUF_FLOATS;
                if (tid == 0) {
                    asm volatile("mbarrier.arrive.expect_tx.shared.b64 _, [%0], %1;"
                                 :: "r"(nm), "r"((uint32_t)(CC * CH_BYTES)) : "memory");
                }
                __syncwarp();
                if (tid < CC) {
                    asm volatile(
                        "cp.async.bulk.shared::cluster.global.mbarrier::complete_tx::bytes "
                        "[%0], [%1], %2, [%3];"
                        :: "r"(smem_u32(nbuf + chan_base(tid))),
                           "l"(nimg + (size_t)tid * HW), "r"((uint32_t)CH_BYTES),
                           "r"(nm) : "memory");
                }
            }
        }

        // ---- wait for current tile (parity flips every 2 iterations) ----
        mbar_wait(smem_u32(&mbar[buf_i]), (k >> 1) & 1);

        const int b  = t >> 6;
        const int c0 = (t & 63) * CC;

        // ---- box coordinates for this tile's batch (read in bu after sync) ----
        if (tid < NBOX) {
            const float* bp = boxes + ((size_t)b * NBOX + tid) * 4;
            int x1 = (int)rintf(bp[0] * (float)PP);   // round-half-even == jnp.round
            int y1 = (int)rintf(bp[1] * (float)PP);
            int x2 = (int)rintf(bp[2] * (float)PP);
            int y2 = (int)rintf(bp[3] * (float)PP);
            bool eqx = (x1 == x2);
            if (eqx && x2 <  PP) x2 += 1;
            if (eqx && x2 >= PP && x1 > 0 && x1 == x2) x1 -= 1;
            bool eqy = (y1 == y2);
            if (eqy && y2 <  PP) y2 += 1;
            if (eqy && y2 >= PP && y1 > 0 && y1 == y2) y1 -= 1;
            bx1[tid] = x1; by1[tid] = y1; bx2[tid] = x2; by2[tid] = y2;
            barea[tid] = (float)((y2 - y1) * (x2 - x1));
        }

        // ---- att: transpose; c4 = tid&7 (512 % 8 == 0), 4 conflict-free LDS
        //      -> 1 STG.128, 128B per-warp segments (R9 proven mapping) ----
        {
            const int c4  = tid & 7;
            const int hw0 = tid >> 3;                  // 0..63
            const float* t0 = tile + chan_base(4 * c4 + 0);
            const float* t1 = tile + chan_base(4 * c4 + 1);
            const float* t2 = tile + chan_base(4 * c4 + 2);
            const float* t3 = tile + chan_base(4 * c4 + 3);
            float* a = att + (size_t)b * HW * CHAN + c0 + (size_t)hw0 * CHAN + 4 * c4;
            #pragma unroll
            for (int hw = hw0; hw < HW; hw += 64, a += 64 * CHAN) {
                float4 v;
                v.x = t0[hw]; v.y = t1[hw]; v.z = t2[hw]; v.w = t3[hw];
                *(float4*)a = v;
            }
        }

        // ---- row prefix: thread per (c, y), natural row order ----
        if (tid < CC * PP) {
            int c = tid / PP, y = tid - c * PP;
            const float* tc  = tile + chan_base(c) + y * PP;
            float*       dst = rpf  + c * RSTR + y * RW;
            dst[0] = 0.0f;
            float acc = 0.0f;
            #pragma unroll
            for (int x = 0; x < PP; x++) { acc += tc[x]; dst[x + 1] = acc; }
        }
        __syncthreads();   // rpf + boxes ready

        // ---- fc: column-sum of full row sums / 196 (one warp, lanes = c) ----
        if (tid < CC) {
            const float* Rc = rpf + tid * RSTR;
            float s = 0.0f;
            #pragma unroll
            for (int y = 0; y < PP; y++) s += Rc[y * RW + PP];
            fc[(size_t)b * CHAN + c0 + tid] = s * (1.0f / (float)HW);
        }

        // ---- bu: vertical accumulation of row-prefix diffs; warp = box,
        //      lane = c (stride 211 conflict-free), uniform y trip count ----
        {
            float* bub = bu + (size_t)b * NBOX * CHAN + c0;
            for (int i = tid; i < NBOX * CC; i += NTHREADS) {
                int r = i >> 5, c = i & 31;
                const float* Rc = rpf + c * RSTR;
                int x1 = bx1[r], y1 = by1[r], x2 = bx2[r], y2 = by2[r];
                float s = 0.0f;
                for (int y = y1; y < y2; y++)
                    s += Rc[y * RW + x2] - Rc[y * RW + x1];
                bub[(size_t)r * CHAN + c] = s / barea[r];
            }
        }
        __syncthreads();   // tile/rpf/boxes drained -> safe to overwrite next iter
    }
}

extern "C" void kernel_launch(void* const* d_in, const int* in_sizes, int n_in,
                              void* d_out, int out_size)
{
    const float* images = (const float*)d_in[0];
    const float* boxes  = (const float*)d_in[1];

    float* out = (float*)d_out;
    float* fc  = out;                                   // [128, 2048]
    float* att = fc  + (size_t)BATCH * CHAN;            // [128, 196, 2048]
    float* bu  = att + (size_t)BATCH * HW * CHAN;       // [128, 36, 2048]

    cudaFuncSetAttribute(fused_pool_transpose_region,
                         cudaFuncAttributeMaxDynamicSharedMemorySize,
                         (int)SMEM_BYTES);

    fused_pool_transpose_region<<<GRID, NTHREADS, SMEM_BYTES>>>(
        images, boxes, fc, att, bu);
}